// round 9
// baseline (speedup 1.0000x reference)
#include <cuda_runtime.h>
#include <math.h>

#define N 4096
#define D 512

// ---------------- scratch (static __device__, per harness rules) -------------
__device__ float  g_fn[(size_t)N * D];      // normalized features, TF32-rounded
__device__ float  g_sims[(size_t)N * N];    // sims[i][q], q = label-sorted position
__device__ double g_pref[(size_t)N * N];    // per-row double inclusive prefix (sorted order)
__device__ float  g_ls[N];                  // sorted labels
__device__ int    g_perm[N];                // perm[q] = original index
__device__ int    g_ipos[N];                // ipos[i]  = position of i in sorted order
__device__ double g_loss[N];                // per-row losses

__device__ __forceinline__ float tf32_round(float x) {
    unsigned r;
    asm("cvt.rna.tf32.f32 %0, %1;" : "=r"(r) : "f"(x));
    return __uint_as_float(r);
}

// ---------------- 1) bitonic sort of labels (single block) -------------------
__global__ void sort_kernel(const float* __restrict__ labels) {
    __shared__ float key[N];
    __shared__ int   idx[N];
    int tid = threadIdx.x;  // 1024 threads
    for (int p = tid; p < N; p += 1024) { key[p] = labels[p]; idx[p] = p; }
    __syncthreads();
    for (int k = 2; k <= N; k <<= 1) {
        for (int j = k >> 1; j > 0; j >>= 1) {
            for (int p = tid; p < N; p += 1024) {
                int q = p ^ j;
                if (q > p) {
                    bool up = ((p & k) == 0);
                    float a = key[p], b = key[q];
                    bool swap = up ? (a > b || (a == b && idx[p] > idx[q]))
                                   : (a < b || (a == b && idx[p] < idx[q]));
                    if (swap) {
                        key[p] = b; key[q] = a;
                        int t2 = idx[p]; idx[p] = idx[q]; idx[q] = t2;
                    }
                }
            }
            __syncthreads();
        }
    }
    for (int p = tid; p < N; p += 1024) {
        g_ls[p] = key[p];
        g_perm[p] = idx[p];
        g_ipos[idx[p]] = p;
    }
}

// ---------------- 2) row normalization, output rounded to TF32 ---------------
__global__ void norm_kernel(const float* __restrict__ X) {
    int i = blockIdx.x, tid = threadIdx.x;  // 128 threads, 512 elems
    const float4* xr = (const float4*)(X + (size_t)i * D);
    float4 v = xr[tid];
    float ss = v.x * v.x + v.y * v.y + v.z * v.z + v.w * v.w;
    #pragma unroll
    for (int o = 16; o > 0; o >>= 1) ss += __shfl_xor_sync(0xffffffffu, ss, o);
    __shared__ float ws[4];
    if ((tid & 31) == 0) ws[tid >> 5] = ss;
    __syncthreads();
    float tot = ws[0] + ws[1] + ws[2] + ws[3];
    float nrm = sqrtf(tot);
    float4 o4 = make_float4(tf32_round(v.x / nrm), tf32_round(v.y / nrm),
                            tf32_round(v.z / nrm), tf32_round(v.w / nrm));
    ((float4*)g_fn)[(size_t)i * (D / 4) + tid] = o4;
}

// ---------------- 3) fused GEMM + exp:  sims[i][q] = exp(f_i . f_perm[q] / T)
// Operands TF32-rounded (products exact in fp32), fp32 FMA accumulation.
#define BM 128
#define BN 128
#define BK 16
__global__ __launch_bounds__(256) void gemm_exp_kernel() {
    __shared__ float As[BK][BM];
    __shared__ float Bs[BK][BN];
    __shared__ int   permS[BN];
    int bm = blockIdx.y, bn = blockIdx.x, tid = threadIdx.x;
    if (tid < BN) permS[tid] = g_perm[bn * BN + tid];
    __syncthreads();
    int tcol = tid & 15, trow = tid >> 4;
    float acc[8][8];
    #pragma unroll
    for (int m = 0; m < 8; m++)
        #pragma unroll
        for (int n = 0; n < 8; n++) acc[m][n] = 0.0f;

    for (int kt = 0; kt < D; kt += BK) {
        #pragma unroll
        for (int l = 0; l < 2; l++) {
            int q = tid + l * 256;
            int row = q >> 2;
            int c4 = (q & 3) * 4;
            float4 va = *(const float4*)&g_fn[(size_t)(bm * BM + row) * D + kt + c4];
            As[c4 + 0][row] = va.x; As[c4 + 1][row] = va.y;
            As[c4 + 2][row] = va.z; As[c4 + 3][row] = va.w;
            float4 vb = *(const float4*)&g_fn[(size_t)permS[row] * D + kt + c4];
            Bs[c4 + 0][row] = vb.x; Bs[c4 + 1][row] = vb.y;
            Bs[c4 + 2][row] = vb.z; Bs[c4 + 3][row] = vb.w;
        }
        __syncthreads();
        #pragma unroll
        for (int k = 0; k < BK; k++) {
            float ar[8], br[8];
            #pragma unroll
            for (int m = 0; m < 8; m++) ar[m] = As[k][trow * 8 + m];
            #pragma unroll
            for (int n = 0; n < 8; n++) br[n] = Bs[k][tcol * 8 + n];
            #pragma unroll
            for (int m = 0; m < 8; m++)
                #pragma unroll
                for (int n = 0; n < 8; n++) acc[m][n] += ar[m] * br[n];
        }
        __syncthreads();
    }
    #pragma unroll
    for (int m = 0; m < 8; m++) {
        int gi = bm * BM + trow * 8 + m;
        #pragma unroll
        for (int n = 0; n < 8; n++) {
            int gp = bn * BN + tcol * 8 + n;
            g_sims[(size_t)gi * N + gp] = expf(acc[m][n] / 0.07f);
        }
    }
}

// ---------------- 4) per-row double inclusive prefix (label-sorted order) ----
// Exact (to ~1e-12) window set-sums; realization-independent. den is then
// reconstructed by grid quantization (see terms kernel).
__global__ void row_scan_kernel() {
    int i = blockIdx.x, tid = threadIdx.x;  // 512 threads, 8 elems each
    const float4* r4 = (const float4*)(g_sims + (size_t)i * N);
    double* prow = g_pref + (size_t)i * N;

    float4 v0 = r4[tid * 2 + 0];
    float4 v1 = r4[tid * 2 + 1];
    double loc[8];
    double s = 0.0;
    s += (double)v0.x; loc[0] = s;
    s += (double)v0.y; loc[1] = s;
    s += (double)v0.z; loc[2] = s;
    s += (double)v0.w; loc[3] = s;
    s += (double)v1.x; loc[4] = s;
    s += (double)v1.y; loc[5] = s;
    s += (double)v1.z; loc[6] = s;
    s += (double)v1.w; loc[7] = s;

    double ws = s;
    #pragma unroll
    for (int o = 1; o < 32; o <<= 1) {
        double v = __shfl_up_sync(0xffffffffu, ws, o);
        if ((tid & 31) >= o) ws += v;
    }
    __shared__ double warpsum[16];
    if ((tid & 31) == 31) warpsum[tid >> 5] = ws;
    __syncthreads();
    if (tid < 16) {
        double w = warpsum[tid];
        #pragma unroll
        for (int o = 1; o < 16; o <<= 1) {
            double v = __shfl_up_sync(0x0000ffffu, w, o);
            if (tid >= o) w += v;
        }
        warpsum[tid] = w;
    }
    __syncthreads();
    double offset = ws - s;  // exclusive within warp
    if (tid >= 32) offset += warpsum[(tid >> 5) - 1];

    int base = tid * 8;
    #pragma unroll
    for (int k = 0; k < 8; k++) prow[base + k] = loc[k] + offset;
}

// ---------------- 5) per-row loss terms, grid-quantized denominators ---------
// Reference realization model: csum[m] = fl32(self_sim + fine_sum) with a
// SINGLE rounding at the 2^20-binade grid (ulp = 0.125). The self_sim (grid
// multiple) cancels, leaving:
//   den = 0.125 * ( rne(St/0.125) - rne(Sm/0.125) )
// where St = total - self, Sm = window_sum - self (exact double set sums).
// den >= 0 always; den == 0 -> masked; den >= 0.125 -> clip never binds.
__global__ void row_terms_kernel(const float* __restrict__ labels) {
    __shared__ float  lsh[N];    // 16 KB sorted labels
    __shared__ double red[512];  // reduction
    int i = blockIdx.x, tid = threadIdx.x;  // 512 threads
    for (int p = tid; p < N; p += 512) lsh[p] = g_ls[p];
    __syncthreads();

    const float li = labels[i];
    const int ipos = g_ipos[i];
    const float*  __restrict__ row  = g_sims + (size_t)i * N;
    const double* __restrict__ prow = g_pref + (size_t)i * N;
    const double selfsim = (double)__ldg(&row[ipos]);
    const double St = __ldg(&prow[N - 1]) - selfsim;
    const double qt = rint(St * 8.0);   // total tail anchor (in grid units)

    double acc = 0.0;
    for (int p = tid; p < N; p += 512) {
        if (p == ipos) continue;  // diagonal mask
        float t = fabsf(li - lsh[p]);
        int a, b;
        if (p > ipos) {
            b = p;
            while (b + 1 < N && fabsf(li - lsh[b + 1]) <= t) b++;  // tie extent
            int lo = 0, hi = ipos;  // leftmost position with dist <= t
            while (lo < hi) {
                int mid = (lo + hi) >> 1;
                if (fabsf(li - lsh[mid]) <= t) hi = mid; else lo = mid + 1;
            }
            a = lo;
        } else {
            a = p;
            while (a > 0 && fabsf(li - lsh[a - 1]) <= t) a--;  // tie extent
            int lo = ipos, hi = N - 1;  // rightmost position with dist <= t
            while (lo < hi) {
                int mid = (lo + hi + 1) >> 1;
                if (fabsf(li - lsh[mid]) <= t) lo = mid; else hi = mid - 1;
            }
            b = lo;
        }
        // window [a,b] (contains self). Sm = window sum excluding self.
        double W  = __ldg(&prow[b]) - (a > 0 ? __ldg(&prow[a - 1]) : 0.0);
        double Sm = W - selfsim;
        double den = (qt - rint(Sm * 8.0)) * 0.125;
        if (den > 0.0) {
            acc += (double)__ldg(&row[p]) / den;
        }
    }

    red[tid] = acc;
    __syncthreads();
    for (int o = 256; o > 0; o >>= 1) {
        if (tid < o) red[tid] += red[tid + o];
        __syncthreads();
    }
    if (tid == 0) g_loss[i] = red[0] / (double)(N - 1);
}

// ---------------- 6) deterministic final reduction ---------------------------
__global__ void final_reduce_kernel(float* __restrict__ out) {
    __shared__ double red[512];
    int tid = threadIdx.x;
    double s = 0.0;
    for (int k = tid; k < N; k += 512) s += g_loss[k];
    red[tid] = s;
    __syncthreads();
    for (int o = 256; o > 0; o >>= 1) {
        if (tid < o) red[tid] += red[tid + o];
        __syncthreads();
    }
    if (tid == 0) out[0] = (float)(red[0] / (double)N);
}

// ---------------- launcher ----------------------------------------------------
extern "C" void kernel_launch(void* const* d_in, const int* in_sizes, int n_in,
                              void* d_out, int out_size) {
    const float* features = (const float*)d_in[0];
    const float* labels   = (const float*)d_in[1];
    float* out = (float*)d_out;

    sort_kernel<<<1, 1024>>>(labels);
    norm_kernel<<<N, 128>>>(features);
    gemm_exp_kernel<<<dim3(N / BN, N / BM), 256>>>();
    row_scan_kernel<<<N, 512>>>();
    row_terms_kernel<<<N, 512>>>(labels);
    final_reduce_kernel<<<1, 512>>>(out);
}

// round 10
// speedup vs baseline: 1.5186x; 1.5186x over previous
#include <cuda_runtime.h>
#include <math.h>

#define N 4096
#define D 512

// ---------------- scratch (static __device__, per harness rules) -------------
__device__ float  g_fn[(size_t)N * D];      // normalized features, TF32-rounded
__device__ float  g_sims[(size_t)N * N];    // sims2[q1][q2], both axes label-sorted
__device__ float  g_ls[N];                  // sorted labels
__device__ int    g_perm[N];                // perm[q] = original index
__device__ int    g_ipos[N];                // ipos[i]  = position of i in sorted order
__device__ double g_loss[N];                // per-row losses

__device__ __forceinline__ float tf32_round(float x) {
    unsigned r;
    asm("cvt.rna.tf32.f32 %0, %1;" : "=r"(r) : "f"(x));
    return __uint_as_float(r);
}

// ---------------- 1) bitonic sort of labels (single block) -------------------
__global__ void sort_kernel(const float* __restrict__ labels) {
    __shared__ float key[N];
    __shared__ int   idx[N];
    int tid = threadIdx.x;  // 1024 threads
    for (int p = tid; p < N; p += 1024) { key[p] = labels[p]; idx[p] = p; }
    __syncthreads();
    for (int k = 2; k <= N; k <<= 1) {
        for (int j = k >> 1; j > 0; j >>= 1) {
            for (int p = tid; p < N; p += 1024) {
                int q = p ^ j;
                if (q > p) {
                    bool up = ((p & k) == 0);
                    float a = key[p], b = key[q];
                    bool swap = up ? (a > b || (a == b && idx[p] > idx[q]))
                                   : (a < b || (a == b && idx[p] < idx[q]));
                    if (swap) {
                        key[p] = b; key[q] = a;
                        int t2 = idx[p]; idx[p] = idx[q]; idx[q] = t2;
                    }
                }
            }
            __syncthreads();
        }
    }
    for (int p = tid; p < N; p += 1024) {
        g_ls[p] = key[p];
        g_perm[p] = idx[p];
        g_ipos[idx[p]] = p;
    }
}

// ---------------- 2) row normalization, output rounded to TF32 ---------------
__global__ void norm_kernel(const float* __restrict__ X) {
    int i = blockIdx.x, tid = threadIdx.x;  // 128 threads, 512 elems
    const float4* xr = (const float4*)(X + (size_t)i * D);
    float4 v = xr[tid];
    float ss = v.x * v.x + v.y * v.y + v.z * v.z + v.w * v.w;
    #pragma unroll
    for (int o = 16; o > 0; o >>= 1) ss += __shfl_xor_sync(0xffffffffu, ss, o);
    __shared__ float ws[4];
    if ((tid & 31) == 0) ws[tid >> 5] = ss;
    __syncthreads();
    float tot = ws[0] + ws[1] + ws[2] + ws[3];
    float nrm = sqrtf(tot);
    float4 o4 = make_float4(tf32_round(v.x / nrm), tf32_round(v.y / nrm),
                            tf32_round(v.z / nrm), tf32_round(v.w / nrm));
    ((float4*)g_fn)[(size_t)i * (D / 4) + tid] = o4;
}

// ---------------- 3) symmetric fused GEMM + exp ------------------------------
// sims2[q1][q2] = exp(dot(f_perm[q1], f_perm[q2]) / T).  Symmetric: compute
// only tile-pairs bi<=bj (528 of 1024), mirror via smem transpose bounce.
// The k-accumulation chain is identical to the full GEMM -> bitwise-same sims.
#define BM 128
#define BN 128
#define BK 16
__global__ __launch_bounds__(256) void gemm_exp_sym_kernel() {
    __shared__ float As[BK][BM];
    __shared__ float Bs[BK][BN];
    __shared__ int   permA[128];
    __shared__ int   permB[128];
    __shared__ float stage[32][129];
    int tid = threadIdx.x;
    int bi = 0, bj = 0;
    {
        int r = blockIdx.x;
        #pragma unroll 1
        for (int b = 0; b < 32; b++) {
            int cnt = 32 - b;
            if (r < cnt) { bi = b; bj = b + r; break; }
            r -= cnt;
        }
    }
    if (tid < 128) permA[tid] = g_perm[bi * 128 + tid];
    else           permB[tid - 128] = g_perm[bj * 128 + (tid - 128)];
    __syncthreads();

    int tcol = tid & 15, trow = tid >> 4;
    float acc[8][8];
    #pragma unroll
    for (int m = 0; m < 8; m++)
        #pragma unroll
        for (int n = 0; n < 8; n++) acc[m][n] = 0.0f;

    for (int kt = 0; kt < D; kt += BK) {
        #pragma unroll
        for (int l = 0; l < 2; l++) {
            int q = tid + l * 256;
            int row = q >> 2;
            int c4 = (q & 3) * 4;
            float4 va = *(const float4*)&g_fn[(size_t)permA[row] * D + kt + c4];
            As[c4 + 0][row] = va.x; As[c4 + 1][row] = va.y;
            As[c4 + 2][row] = va.z; As[c4 + 3][row] = va.w;
            float4 vb = *(const float4*)&g_fn[(size_t)permB[row] * D + kt + c4];
            Bs[c4 + 0][row] = vb.x; Bs[c4 + 1][row] = vb.y;
            Bs[c4 + 2][row] = vb.z; Bs[c4 + 3][row] = vb.w;
        }
        __syncthreads();
        #pragma unroll
        for (int k = 0; k < BK; k++) {
            float ar[8], br[8];
            #pragma unroll
            for (int m = 0; m < 8; m++) ar[m] = As[k][trow * 8 + m];
            #pragma unroll
            for (int n = 0; n < 8; n++) br[n] = Bs[k][tcol * 8 + n];
            #pragma unroll
            for (int m = 0; m < 8; m++)
                #pragma unroll
                for (int n = 0; n < 8; n++) acc[m][n] += ar[m] * br[n];
        }
        __syncthreads();
    }

    // exp epilogue (in place), then direct write
    #pragma unroll
    for (int m = 0; m < 8; m++)
        #pragma unroll
        for (int n = 0; n < 8; n++) acc[m][n] = expf(acc[m][n] / 0.07f);

    #pragma unroll
    for (int m = 0; m < 8; m++) {
        int gq1 = bi * 128 + trow * 8 + m;
        #pragma unroll
        for (int n = 0; n < 8; n++) {
            int gq2 = bj * 128 + tcol * 8 + n;
            g_sims[(size_t)gq1 * N + gq2] = acc[m][n];
        }
    }

    // mirror write via transpose bounce (coalesced)
    if (bi != bj) {
        #pragma unroll 1
        for (int cc = 0; cc < 4; cc++) {
            __syncthreads();
            if ((trow >> 2) == cc) {
                #pragma unroll
                for (int m = 0; m < 8; m++) {
                    int r = trow * 8 + m - cc * 32;
                    #pragma unroll
                    for (int n = 0; n < 8; n++)
                        stage[r][tcol * 8 + n] = acc[m][n];
                }
            }
            __syncthreads();
            for (int j = tid; j < 32 * 128; j += 256) {
                int rr = j & 31, cp = j >> 5;
                g_sims[(size_t)(bj * 128 + cp) * N + bi * 128 + cc * 32 + rr] = stage[rr][cp];
            }
        }
    }
}

// ---------------- 4) fused per-row prefix scan + loss terms ------------------
// Prefix sums (double, bitwise-identical code to the standalone scan) live in
// dynamic smem; terms read them directly. Row index IS the sorted position.
__global__ __launch_bounds__(512) void scan_terms_kernel() {
    extern __shared__ char dsm[];
    double* spref = (double*)dsm;                    // 32 KB
    float*  lsh   = (float*)(dsm + 32768);           // 16 KB
    double* red   = (double*)(dsm + 32768 + 16384);  // 4 KB
    __shared__ double warpsum[16];

    int q1 = blockIdx.x, tid = threadIdx.x;  // 512 threads
    const float* __restrict__ row = g_sims + (size_t)q1 * N;

    for (int p = tid; p < N; p += 512) lsh[p] = g_ls[p];

    // ---- prefix scan (same arithmetic as before -> bitwise-same values) ----
    const float4* r4 = (const float4*)row;
    float4 v0 = r4[tid * 2 + 0];
    float4 v1 = r4[tid * 2 + 1];
    double loc[8];
    double s = 0.0;
    s += (double)v0.x; loc[0] = s;
    s += (double)v0.y; loc[1] = s;
    s += (double)v0.z; loc[2] = s;
    s += (double)v0.w; loc[3] = s;
    s += (double)v1.x; loc[4] = s;
    s += (double)v1.y; loc[5] = s;
    s += (double)v1.z; loc[6] = s;
    s += (double)v1.w; loc[7] = s;

    double ws = s;
    #pragma unroll
    for (int o = 1; o < 32; o <<= 1) {
        double v = __shfl_up_sync(0xffffffffu, ws, o);
        if ((tid & 31) >= o) ws += v;
    }
    if ((tid & 31) == 31) warpsum[tid >> 5] = ws;
    __syncthreads();
    if (tid < 16) {
        double w = warpsum[tid];
        #pragma unroll
        for (int o = 1; o < 16; o <<= 1) {
            double v = __shfl_up_sync(0x0000ffffu, w, o);
            if (tid >= o) w += v;
        }
        warpsum[tid] = w;
    }
    __syncthreads();
    double offset = ws - s;  // exclusive within warp
    if (tid >= 32) offset += warpsum[(tid >> 5) - 1];
    int base = tid * 8;
    #pragma unroll
    for (int k = 0; k < 8; k++) spref[base + k] = loc[k] + offset;
    __syncthreads();

    // ---- terms: grid-quantized denominators --------------------------------
    const float li = lsh[q1];
    const int ipos = q1;
    const double selfsim = (double)__ldg(&row[ipos]);
    const double St = spref[N - 1] - selfsim;
    const double qt = rint(St * 8.0);

    double acc = 0.0;
    for (int p = tid; p < N; p += 512) {
        if (p == ipos) continue;  // diagonal mask
        float t = fabsf(li - lsh[p]);
        int a, b;
        if (p > ipos) {
            b = p;
            while (b + 1 < N && fabsf(li - lsh[b + 1]) <= t) b++;  // tie extent
            int lo = 0, hi = ipos;
            while (lo < hi) {
                int mid = (lo + hi) >> 1;
                if (fabsf(li - lsh[mid]) <= t) hi = mid; else lo = mid + 1;
            }
            a = lo;
        } else {
            a = p;
            while (a > 0 && fabsf(li - lsh[a - 1]) <= t) a--;  // tie extent
            int lo = ipos, hi = N - 1;
            while (lo < hi) {
                int mid = (lo + hi + 1) >> 1;
                if (fabsf(li - lsh[mid]) <= t) lo = mid; else hi = mid - 1;
            }
            b = lo;
        }
        double W  = spref[b] - (a > 0 ? spref[a - 1] : 0.0);
        double Sm = W - selfsim;
        double den = (qt - rint(Sm * 8.0)) * 0.125;
        if (den > 0.0) {
            acc += (double)__ldg(&row[p]) / den;
        }
    }

    red[tid] = acc;
    __syncthreads();
    for (int o = 256; o > 0; o >>= 1) {
        if (tid < o) red[tid] += red[tid + o];
        __syncthreads();
    }
    if (tid == 0) g_loss[q1] = red[0] / (double)(N - 1);
}

// ---------------- 5) deterministic final reduction ---------------------------
__global__ void final_reduce_kernel(float* __restrict__ out) {
    __shared__ double red[512];
    int tid = threadIdx.x;
    double s = 0.0;
    for (int k = tid; k < N; k += 512) s += g_loss[k];
    red[tid] = s;
    __syncthreads();
    for (int o = 256; o > 0; o >>= 1) {
        if (tid < o) red[tid] += red[tid + o];
        __syncthreads();
    }
    if (tid == 0) out[0] = (float)(red[0] / (double)N);
}

// ---------------- launcher ----------------------------------------------------
extern "C" void kernel_launch(void* const* d_in, const int* in_sizes, int n_in,
                              void* d_out, int out_size) {
    const float* features = (const float*)d_in[0];
    const float* labels   = (const float*)d_in[1];
    float* out = (float*)d_out;

    cudaFuncSetAttribute(scan_terms_kernel,
                         cudaFuncAttributeMaxDynamicSharedMemorySize, 53248);

    sort_kernel<<<1, 1024>>>(labels);
    norm_kernel<<<N, 128>>>(features);
    gemm_exp_sym_kernel<<<528, 256>>>();
    scan_terms_kernel<<<N, 512, 53248>>>();
    final_reduce_kernel<<<1, 512>>>(out);
}

// round 11
// speedup vs baseline: 1.9118x; 1.2589x over previous
#include <cuda_runtime.h>
#include <math.h>

#define N 4096
#define D 512

// ---------------- scratch (static __device__, per harness rules) -------------
__device__ float  g_fn[(size_t)N * D];      // normalized features, TF32-rounded
__device__ float  g_sims[(size_t)N * N];    // sims2[q1][q2], both axes label-sorted
__device__ float  g_ls[N];                  // sorted labels
__device__ int    g_perm[N];                // perm[q] = original index
__device__ int    g_ipos[N];                // ipos[i]  = position of i in sorted order
__device__ double g_loss[N];                // per-row losses

__device__ __forceinline__ float tf32_round(float x) {
    unsigned r;
    asm("cvt.rna.tf32.f32 %0, %1;" : "=r"(r) : "f"(x));
    return __uint_as_float(r);
}

// m16n8k8 TF32 MMA, fp32 accumulate (D = A(16x8) * B(8x8) + D)
__device__ __forceinline__ void mma_tf32(float* c, const unsigned* a, const unsigned* b) {
    asm volatile(
        "mma.sync.aligned.m16n8k8.row.col.f32.tf32.tf32.f32 "
        "{%0,%1,%2,%3}, {%4,%5,%6,%7}, {%8,%9}, {%0,%1,%2,%3};\n"
        : "+f"(c[0]), "+f"(c[1]), "+f"(c[2]), "+f"(c[3])
        : "r"(a[0]), "r"(a[1]), "r"(a[2]), "r"(a[3]), "r"(b[0]), "r"(b[1]));
}

// ---------------- 1) bitonic sort of labels (single block) -------------------
__global__ void sort_kernel(const float* __restrict__ labels) {
    __shared__ float key[N];
    __shared__ int   idx[N];
    int tid = threadIdx.x;  // 1024 threads
    for (int p = tid; p < N; p += 1024) { key[p] = labels[p]; idx[p] = p; }
    __syncthreads();
    for (int k = 2; k <= N; k <<= 1) {
        for (int j = k >> 1; j > 0; j >>= 1) {
            for (int p = tid; p < N; p += 1024) {
                int q = p ^ j;
                if (q > p) {
                    bool up = ((p & k) == 0);
                    float a = key[p], b = key[q];
                    bool swap = up ? (a > b || (a == b && idx[p] > idx[q]))
                                   : (a < b || (a == b && idx[p] < idx[q]));
                    if (swap) {
                        key[p] = b; key[q] = a;
                        int t2 = idx[p]; idx[p] = idx[q]; idx[q] = t2;
                    }
                }
            }
            __syncthreads();
        }
    }
    for (int p = tid; p < N; p += 1024) {
        g_ls[p] = key[p];
        g_perm[p] = idx[p];
        g_ipos[idx[p]] = p;
    }
}

// ---------------- 2) row normalization, output rounded to TF32 ---------------
__global__ void norm_kernel(const float* __restrict__ X) {
    int i = blockIdx.x, tid = threadIdx.x;  // 128 threads, 512 elems
    const float4* xr = (const float4*)(X + (size_t)i * D);
    float4 v = xr[tid];
    float ss = v.x * v.x + v.y * v.y + v.z * v.z + v.w * v.w;
    #pragma unroll
    for (int o = 16; o > 0; o >>= 1) ss += __shfl_xor_sync(0xffffffffu, ss, o);
    __shared__ float ws[4];
    if ((tid & 31) == 0) ws[tid >> 5] = ss;
    __syncthreads();
    float tot = ws[0] + ws[1] + ws[2] + ws[3];
    float nrm = sqrtf(tot);
    float4 o4 = make_float4(tf32_round(v.x / nrm), tf32_round(v.y / nrm),
                            tf32_round(v.z / nrm), tf32_round(v.w / nrm));
    ((float4*)g_fn)[(size_t)i * (D / 4) + tid] = o4;
}

// ---------------- 3) symmetric tensor-core GEMM + exp ------------------------
// sims2[q1][q2] = exp(dot(f_perm[q1], f_perm[q2]) / T) via mma.sync tf32.
// Inputs already TF32-rounded -> products exact; fp32 accumulation.
// Only tile-pairs bi<=bj computed; mirror via smem transpose bounce.
#define KT 32
__global__ __launch_bounds__(256) void gemm_mma_sym_kernel() {
    __shared__ float As[128][36];   // m-major, pad 36 -> conflict-free frag LDS
    __shared__ float Bs[128][36];
    __shared__ int   permA[128];
    __shared__ int   permB[128];
    int tid = threadIdx.x;
    int lane = tid & 31, wid = tid >> 5;
    int warp_m = wid & 3;    // 4 warps over 128 rows (32 each)
    int warp_n = wid >> 2;   // 2 warps over 128 cols (64 each)

    int bi = 0, bj = 0;
    {
        int r = blockIdx.x;
        #pragma unroll 1
        for (int b = 0; b < 32; b++) {
            int cnt = 32 - b;
            if (r < cnt) { bi = b; bj = b + r; break; }
            r -= cnt;
        }
    }
    if (tid < 128) permA[tid] = g_perm[bi * 128 + tid];
    else           permB[tid - 128] = g_perm[bj * 128 + (tid - 128)];
    __syncthreads();

    float acc[2][8][4];
    #pragma unroll
    for (int mf = 0; mf < 2; mf++)
        #pragma unroll
        for (int nf = 0; nf < 8; nf++)
            #pragma unroll
            for (int r = 0; r < 4; r++) acc[mf][nf][r] = 0.0f;

    for (int kt = 0; kt < D; kt += KT) {
        // load tiles (coalesced float4, STS.128 into padded m-major smem)
        #pragma unroll
        for (int l = 0; l < 4; l++) {
            int j = tid + l * 256;
            int row = j >> 3;
            int c4 = (j & 7) * 4;
            float4 va = *(const float4*)&g_fn[(size_t)permA[row] * D + kt + c4];
            *(float4*)&As[row][c4] = va;
            float4 vb = *(const float4*)&g_fn[(size_t)permB[row] * D + kt + c4];
            *(float4*)&Bs[row][c4] = vb;
        }
        __syncthreads();
        #pragma unroll
        for (int ks = 0; ks < 4; ks++) {
            int k0 = ks * 8 + (lane & 3);
            unsigned a[2][4], b[8][2];
            #pragma unroll
            for (int mf = 0; mf < 2; mf++) {
                int m0 = warp_m * 32 + mf * 16 + (lane >> 2);
                a[mf][0] = __float_as_uint(As[m0][k0]);
                a[mf][1] = __float_as_uint(As[m0 + 8][k0]);
                a[mf][2] = __float_as_uint(As[m0][k0 + 4]);
                a[mf][3] = __float_as_uint(As[m0 + 8][k0 + 4]);
            }
            #pragma unroll
            for (int nf = 0; nf < 8; nf++) {
                int n0 = warp_n * 64 + nf * 8 + (lane >> 2);
                b[nf][0] = __float_as_uint(Bs[n0][k0]);
                b[nf][1] = __float_as_uint(Bs[n0][k0 + 4]);
            }
            #pragma unroll
            for (int mf = 0; mf < 2; mf++)
                #pragma unroll
                for (int nf = 0; nf < 8; nf++)
                    mma_tf32(acc[mf][nf], a[mf], b[nf]);
        }
        __syncthreads();
    }

    // exp epilogue in registers
    #pragma unroll
    for (int mf = 0; mf < 2; mf++)
        #pragma unroll
        for (int nf = 0; nf < 8; nf++)
            #pragma unroll
            for (int r = 0; r < 4; r++)
                acc[mf][nf][r] = expf(acc[mf][nf][r] / 0.07f);

    // direct writes: fragment (mf,nf,r) -> (row_local, col_local)
    #pragma unroll
    for (int mf = 0; mf < 2; mf++) {
        #pragma unroll
        for (int r = 0; r < 4; r++) {
            int row_local = warp_m * 32 + mf * 16 + (lane >> 2) + ((r >> 1) ? 8 : 0);
            int gq1 = bi * 128 + row_local;
            #pragma unroll
            for (int nf = 0; nf < 8; nf++) {
                int col_local = warp_n * 64 + nf * 8 + (lane & 3) * 2 + (r & 1);
                g_sims[(size_t)gq1 * N + bj * 128 + col_local] = acc[mf][nf][r];
            }
        }
    }

    // mirror write via transpose bounce (stage aliases As: 129*32*4 <= sizeof(As))
    if (bi != bj) {
        float (*stage)[129] = (float(*)[129])&As[0][0];
        #pragma unroll 1
        for (int cc = 0; cc < 4; cc++) {
            __syncthreads();
            if (warp_m == cc) {   // strip rows cc*32 .. cc*32+31
                #pragma unroll
                for (int mf = 0; mf < 2; mf++) {
                    #pragma unroll
                    for (int r = 0; r < 4; r++) {
                        int rr = mf * 16 + (lane >> 2) + ((r >> 1) ? 8 : 0);
                        #pragma unroll
                        for (int nf = 0; nf < 8; nf++) {
                            int col_local = warp_n * 64 + nf * 8 + (lane & 3) * 2 + (r & 1);
                            stage[rr][col_local] = acc[mf][nf][r];
                        }
                    }
                }
            }
            __syncthreads();
            for (int j = tid; j < 32 * 128; j += 256) {
                int rr = j & 31, cp = j >> 5;
                g_sims[(size_t)(bj * 128 + cp) * N + bi * 128 + cc * 32 + rr] = stage[rr][cp];
            }
        }
    }
}

// ---------------- 4) fused per-row prefix scan + loss terms ------------------
__global__ __launch_bounds__(512) void scan_terms_kernel() {
    extern __shared__ char dsm[];
    double* spref = (double*)dsm;                    // 32 KB
    float*  lsh   = (float*)(dsm + 32768);           // 16 KB
    double* red   = (double*)(dsm + 32768 + 16384);  // 4 KB
    __shared__ double warpsum[16];

    int q1 = blockIdx.x, tid = threadIdx.x;  // 512 threads
    const float* __restrict__ row = g_sims + (size_t)q1 * N;

    for (int p = tid; p < N; p += 512) lsh[p] = g_ls[p];

    // ---- prefix scan (bitwise-same arithmetic as R9/R10) -------------------
    const float4* r4 = (const float4*)row;
    float4 v0 = r4[tid * 2 + 0];
    float4 v1 = r4[tid * 2 + 1];
    double loc[8];
    double s = 0.0;
    s += (double)v0.x; loc[0] = s;
    s += (double)v0.y; loc[1] = s;
    s += (double)v0.z; loc[2] = s;
    s += (double)v0.w; loc[3] = s;
    s += (double)v1.x; loc[4] = s;
    s += (double)v1.y; loc[5] = s;
    s += (double)v1.z; loc[6] = s;
    s += (double)v1.w; loc[7] = s;

    double ws = s;
    #pragma unroll
    for (int o = 1; o < 32; o <<= 1) {
        double v = __shfl_up_sync(0xffffffffu, ws, o);
        if ((tid & 31) >= o) ws += v;
    }
    if ((tid & 31) == 31) warpsum[tid >> 5] = ws;
    __syncthreads();
    if (tid < 16) {
        double w = warpsum[tid];
        #pragma unroll
        for (int o = 1; o < 16; o <<= 1) {
            double v = __shfl_up_sync(0x0000ffffu, w, o);
            if (tid >= o) w += v;
        }
        warpsum[tid] = w;
    }
    __syncthreads();
    double offset = ws - s;  // exclusive within warp
    if (tid >= 32) offset += warpsum[(tid >> 5) - 1];
    int base = tid * 8;
    #pragma unroll
    for (int k = 0; k < 8; k++) spref[base + k] = loc[k] + offset;
    __syncthreads();

    // ---- terms: grid-quantized denominators --------------------------------
    const float li = lsh[q1];
    const int ipos = q1;
    const double selfsim = (double)__ldg(&row[ipos]);
    const double St = spref[N - 1] - selfsim;
    const double qt = rint(St * 8.0);

    double acc = 0.0;
    for (int p = tid; p < N; p += 512) {
        if (p == ipos) continue;  // diagonal mask
        float t = fabsf(li - lsh[p]);
        int a, b;
        if (p > ipos) {
            b = p;
            while (b + 1 < N && fabsf(li - lsh[b + 1]) <= t) b++;  // tie extent
            int lo = 0, hi = ipos;
            while (lo < hi) {
                int mid = (lo + hi) >> 1;
                if (fabsf(li - lsh[mid]) <= t) hi = mid; else lo = mid + 1;
            }
            a = lo;
        } else {
            a = p;
            while (a > 0 && fabsf(li - lsh[a - 1]) <= t) a--;  // tie extent
            int lo = ipos, hi = N - 1;
            while (lo < hi) {
                int mid = (lo + hi + 1) >> 1;
                if (fabsf(li - lsh[mid]) <= t) lo = mid; else hi = mid - 1;
            }
            b = lo;
        }
        double W  = spref[b] - (a > 0 ? spref[a - 1] : 0.0);
        double Sm = W - selfsim;
        double den = (qt - rint(Sm * 8.0)) * 0.125;
        if (den > 0.0) {
            acc += (double)__ldg(&row[p]) / den;
        }
    }

    red[tid] = acc;
    __syncthreads();
    for (int o = 256; o > 0; o >>= 1) {
        if (tid < o) red[tid] += red[tid + o];
        __syncthreads();
    }
    if (tid == 0) g_loss[q1] = red[0] / (double)(N - 1);
}

// ---------------- 5) deterministic final reduction ---------------------------
__global__ void final_reduce_kernel(float* __restrict__ out) {
    __shared__ double red[512];
    int tid = threadIdx.x;
    double s = 0.0;
    for (int k = tid; k < N; k += 512) s += g_loss[k];
    red[tid] = s;
    __syncthreads();
    for (int o = 256; o > 0; o >>= 1) {
        if (tid < o) red[tid] += red[tid + o];
        __syncthreads();
    }
    if (tid == 0) out[0] = (float)(red[0] / (double)N);
}

// ---------------- launcher ----------------------------------------------------
extern "C" void kernel_launch(void* const* d_in, const int* in_sizes, int n_in,
                              void* d_out, int out_size) {
    const float* features = (const float*)d_in[0];
    const float* labels   = (const float*)d_in[1];
    float* out = (float*)d_out;

    cudaFuncSetAttribute(scan_terms_kernel,
                         cudaFuncAttributeMaxDynamicSharedMemorySize, 53248);

    sort_kernel<<<1, 1024>>>(labels);
    norm_kernel<<<N, 128>>>(features);
    gemm_mma_sym_kernel<<<528, 256>>>();
    scan_terms_kernel<<<N, 512, 53248>>>();
    final_reduce_kernel<<<1, 512>>>(out);
}